// round 3
// baseline (speedup 1.0000x reference)
#include <cuda_runtime.h>
#include <cstdint>

// StratifiedRaysampler (fused, L2-residency-aware):
//   z_j = 0.1 + j * (5.9/127),  j in [0,128)
//   points[i,j,c]  = z_j * directions[i,c] / directions[i,2]
//   lengths[i,j,0] = z_j
// d_out layout: [points (N_RAYS*128*3 f32)] ++ [lengths (N_RAYS*128 f32)]
//
// One warp per ray. Points stores use L2::evict_first (pure 402MB stream,
// never re-read within the window). Lengths stores use L2::evict_last so the
// 134MB lengths region stays dirty-resident in the ~126MB L2 across graph
// replays, avoiding most of its DRAM writeback traffic.

#define N_PTS 128
#define MIN_DEPTH 0.1f
#define Z_STEP (5.9f / 127.0f)

__device__ __forceinline__ void st_policy_v4(float4* addr, float4 v, uint64_t pol) {
    asm volatile(
        "st.global.L2::cache_hint.v4.f32 [%0], {%1, %2, %3, %4}, %5;"
        :: "l"(addr), "f"(v.x), "f"(v.y), "f"(v.z), "f"(v.w), "l"(pol)
        : "memory");
}

__global__ void __launch_bounds__(256) fused_raysampler_kernel(
    const float* __restrict__ dirs,
    float* __restrict__ points_out,
    float* __restrict__ lengths_out,
    unsigned n_rays)
{
    unsigned gtid = blockIdx.x * blockDim.x + threadIdx.x;
    unsigned ray  = gtid >> 5;
    unsigned lane = gtid & 31u;
    if (ray >= n_rays) return;

    uint64_t pol_first, pol_last;
    asm volatile("createpolicy.fractional.L2::evict_first.b64 %0, 1.0;" : "=l"(pol_first));
    asm volatile("createpolicy.fractional.L2::evict_last.b64 %0, 1.0;"  : "=l"(pol_last));

    // Warp-uniform loads (L1 broadcast across the warp)
    float d0 = __ldg(&dirs[ray * 3u + 0u]);
    float d1 = __ldg(&dirs[ray * 3u + 1u]);
    float d2 = __ldg(&dirs[ray * 3u + 2u]);
    float inv = 1.0f / d2;
    float s0 = d0 * inv;
    float s1 = d1 * inv;
    // s2 = d2/d2 = 1.0f

    float4* pbase = reinterpret_cast<float4*>(points_out + (size_t)ray * 384u);

    // Single integer division; advance (j, c) incrementally across k.
    unsigned e0 = 4u * lane;          // k = 0 element index
    unsigned j  = e0 / 3u;
    unsigned c  = e0 - 3u * j;

#pragma unroll
    for (unsigned k = 0; k < 3; ++k) {
        unsigned jj = j, cc = c;
        float v[4];
#pragma unroll
        for (int m = 0; m < 4; ++m) {
            float z = __fmaf_rn((float)jj, Z_STEP, MIN_DEPTH);
            float s = (cc == 0u) ? s0 : ((cc == 1u) ? s1 : 1.0f);
            v[m] = z * s;
            if (++cc == 3u) { cc = 0u; ++jj; }
        }
        st_policy_v4(pbase + 32u * k + lane, make_float4(v[0], v[1], v[2], v[3]), pol_first);

        // advance by 128 elements = 42 points + 2 elements (mod 3)
        c += 2u;
        if (c >= 3u) { c -= 3u; j += 43u; } else { j += 42u; }
    }

    // lengths: lane l -> z values [4l, 4l+3], keep resident in L2
    {
        float jb = (float)(4u * lane);
        float4 lv;
        lv.x = __fmaf_rn(jb + 0.0f, Z_STEP, MIN_DEPTH);
        lv.y = __fmaf_rn(jb + 1.0f, Z_STEP, MIN_DEPTH);
        lv.z = __fmaf_rn(jb + 2.0f, Z_STEP, MIN_DEPTH);
        lv.w = __fmaf_rn(jb + 3.0f, Z_STEP, MIN_DEPTH);
        st_policy_v4(reinterpret_cast<float4*>(lengths_out) + (size_t)ray * 32u + lane,
                     lv, pol_last);
    }
}

extern "C" void kernel_launch(void* const* d_in, const int* in_sizes, int n_in,
                              void* d_out, int out_size) {
    // inputs: [0] origins (unused), [1] directions
    const float* dirs = (const float*)d_in[1];
    float* out = (float*)d_out;

    unsigned n_rays = (unsigned)(in_sizes[1] / 3);            // 262144
    size_t points_elems = (size_t)n_rays * N_PTS * 3;         // 100663296
    float* lengths_out = out + points_elems;

    unsigned threads = 256;                                   // 8 warps = 8 rays per block
    unsigned blocks = (n_rays * 32u + threads - 1) / threads; // 32768
    fused_raysampler_kernel<<<blocks, threads>>>(dirs, out, lengths_out, n_rays);
}